// round 10
// baseline (speedup 1.0000x reference)
#include <cuda_runtime.h>
#include <cuda_bf16.h>
#include <math_constants.h>

// VQ forward: z (B,256) f32, embed (512,256) f32.
// out = [ quantized (B*256) | codes (B, as float) | commit (1) ]  (float32)
//
// Numerics model: eager jax on XLA:GPU (GB300 container).
//   dot:    cuBLAS SIMT sgemm == single-accumulator fp32 fma chain, k asc
//   z_sq/e_sq: XLA:GPU row-reduce emitter, row=256, vec=2, threads_x=128:
//              leaf t: x[2t]^2 + x[2t+1]^2  (separate mul/mul/add)
//              in-warp shfl_down tree 16,8,4,2,1
//              cross-warp (4 partials, zero-padded 32-lane tree)
//   dist = (z_sq - (2.0f*dot)) + e_sq  (separately rounded ops)
//   argmin: strict <, ascending, tie -> lower index
//   quantized = z + (q - z), separately rounded
//
// NOTE: device globals are only referenced from device code (R8 bug: passing
// a __device__ symbol as a host-side kernel arg yields a garbage pointer).

#define D_DIM 256
#define K_CODES 512
#define TM 64
#define TN 64
#define TK 16
#define NTHREADS 256
#define B_MAX 262144

__device__ float g_esq[K_CODES];
__device__ float g_zsq[B_MAX];
__device__ float g_partials[8192];

// ---- f32x2 packed helpers (sm_10x) ----
__device__ __forceinline__ unsigned long long pk2(float lo, float hi) {
    unsigned long long r;
    asm("mov.b64 %0, {%1, %2};" : "=l"(r) : "f"(lo), "f"(hi));
    return r;
}
__device__ __forceinline__ void fma2(unsigned long long& d,
                                     unsigned long long a,
                                     unsigned long long b) {
    asm("fma.rn.f32x2 %0, %1, %2, %0;" : "+l"(d) : "l"(a), "l"(b));
}
__device__ __forceinline__ float2 upk2(unsigned long long v) {
    float2 f;
    asm("mov.b64 {%0, %1}, %2;" : "=f"(f.x), "=f"(f.y) : "l"(v));
    return f;
}

// XLA:GPU row-reduce replica for sum(x*x) over a 256-float row.
// 128 threads per row (2 rows per 256-thread block).
// dest==0 -> g_esq, dest==1 -> g_zsq  (symbols referenced in device code only)
__global__ void k_rowsq_xla(const float* __restrict__ x, int rows, int dest) {
    __shared__ float w[8];               // 4 warp partials per row group
    const unsigned full = 0xffffffffu;
    int grp = threadIdx.x >> 7;          // row within block: 0/1
    int t = threadIdx.x & 127;           // thread within row
    long row = (long)blockIdx.x * 2 + grp;

    float s = 0.f;
    if (row < rows) {
        const float2 v = *(const float2*)(x + row * D_DIM + 2 * t);
        s = __fadd_rn(__fmul_rn(v.x, v.x), __fmul_rn(v.y, v.y));
    }
    // in-warp tree 16,8,4,2,1
    s = __fadd_rn(s, __shfl_down_sync(full, s, 16));
    s = __fadd_rn(s, __shfl_down_sync(full, s, 8));
    s = __fadd_rn(s, __shfl_down_sync(full, s, 4));
    s = __fadd_rn(s, __shfl_down_sync(full, s, 2));
    s = __fadd_rn(s, __shfl_down_sync(full, s, 1));
    if ((threadIdx.x & 31) == 0) w[threadIdx.x >> 5] = s;
    __syncthreads();
    // cross-warp: first warp of each group, lanes 0..3 hold w0..w3, pad 0.
    if ((t >> 5) == 0) {
        int lane = t & 31;
        float v = (lane < 4) ? w[grp * 4 + lane] : 0.f;
        v = __fadd_rn(v, __shfl_down_sync(full, v, 16));
        v = __fadd_rn(v, __shfl_down_sync(full, v, 8));
        v = __fadd_rn(v, __shfl_down_sync(full, v, 4));
        v = __fadd_rn(v, __shfl_down_sync(full, v, 2));
        v = __fadd_rn(v, __shfl_down_sync(full, v, 1));
        if (lane == 0 && row < rows) {
            if (dest == 0) g_esq[row] = v;
            else           g_zsq[row] = v;
        }
    }
}

__global__ __launch_bounds__(NTHREADS)
void k_main(const float* __restrict__ z, const float* __restrict__ embed,
            float* __restrict__ out, int B, int write_codes) {
    __shared__ __align__(16) float Zs[TK][TM];
    __shared__ __align__(16) float Es[TK][TN];
    __shared__ float sMin[TM][16];
    __shared__ int   sIdx[TM][16];
    __shared__ int   sCode[TM];
    __shared__ float sPart[NTHREADS];
    __shared__ float sZsq[TM];

    const int tid = threadIdx.x;
    const int tx = tid & 15;          // col group 0..15 (4 cols each)
    const int ty = tid >> 4;          // row group 0..15 (4 rows each)
    const long rowBase = (long)blockIdx.x * TM;

    if (tid < TM) sZsq[tid] = g_zsq[rowBase + tid];

    float rmin[4];
    int   ridx[4];
#pragma unroll
    for (int r = 0; r < 4; r++) { rmin[r] = CUDART_INF_F; ridx[r] = 0; }

    const int mLd = tid >> 2;         // 0..63 : row/code index for tile loads
    const int kq  = tid & 3;          // 0..3  : which float4 along k

    for (int ct = 0; ct < K_CODES / TN; ++ct) {
        unsigned long long acc[4][2];
#pragma unroll
        for (int r = 0; r < 4; r++) { acc[r][0] = 0ull; acc[r][1] = 0ull; }

        for (int kt = 0; kt < D_DIM / TK; ++kt) {
            // ---- load tiles (transposed into [k][m]), full fp32 ----
            float4 zv = *(const float4*)(z + (rowBase + mLd) * D_DIM + kt * TK + kq * 4);
            Zs[kq * 4 + 0][mLd] = zv.x;
            Zs[kq * 4 + 1][mLd] = zv.y;
            Zs[kq * 4 + 2][mLd] = zv.z;
            Zs[kq * 4 + 3][mLd] = zv.w;
            float4 ev = *(const float4*)(embed + (long)(ct * TN + mLd) * D_DIM + kt * TK + kq * 4);
            Es[kq * 4 + 0][mLd] = ev.x;
            Es[kq * 4 + 1][mLd] = ev.y;
            Es[kq * 4 + 2][mLd] = ev.z;
            Es[kq * 4 + 3][mLd] = ev.w;
            __syncthreads();

            // dot: single-accumulator fma chain, k ascending
#pragma unroll
            for (int k = 0; k < TK; k++) {
                float4 za = *(const float4*)&Zs[k][ty * 4];
                float4 ea = *(const float4*)&Es[k][tx * 4];
                unsigned long long b01 = pk2(ea.x, ea.y);
                unsigned long long b23 = pk2(ea.z, ea.w);
                unsigned long long a0 = pk2(za.x, za.x);
                unsigned long long a1 = pk2(za.y, za.y);
                unsigned long long a2 = pk2(za.z, za.z);
                unsigned long long a3 = pk2(za.w, za.w);
                fma2(acc[0][0], a0, b01); fma2(acc[0][1], a0, b23);
                fma2(acc[1][0], a1, b01); fma2(acc[1][1], a1, b23);
                fma2(acc[2][0], a2, b01); fma2(acc[2][1], a2, b23);
                fma2(acc[3][0], a3, b01); fma2(acc[3][1], a3, b23);
            }
            __syncthreads();
        }

        // ---- dist = (z_sq - (2*dot)) + e_sq, separately rounded.
        //      Running argmin, cols ascending => first-min tie rule. ----
        int cb = ct * TN + tx * 4;
        float e0 = g_esq[cb + 0];
        float e1 = g_esq[cb + 1];
        float e2 = g_esq[cb + 2];
        float e3 = g_esq[cb + 3];
#pragma unroll
        for (int r = 0; r < 4; r++) {
            float zs = sZsq[ty * 4 + r];
            float2 d01 = upk2(acc[r][0]);
            float2 d23 = upk2(acc[r][1]);
            float s0 = __fadd_rn(__fsub_rn(zs, __fmul_rn(2.0f, d01.x)), e0);
            float s1 = __fadd_rn(__fsub_rn(zs, __fmul_rn(2.0f, d01.y)), e1);
            float s2 = __fadd_rn(__fsub_rn(zs, __fmul_rn(2.0f, d23.x)), e2);
            float s3 = __fadd_rn(__fsub_rn(zs, __fmul_rn(2.0f, d23.y)), e3);
            if (s0 < rmin[r]) { rmin[r] = s0; ridx[r] = cb + 0; }
            if (s1 < rmin[r]) { rmin[r] = s1; ridx[r] = cb + 1; }
            if (s2 < rmin[r]) { rmin[r] = s2; ridx[r] = cb + 2; }
            if (s3 < rmin[r]) { rmin[r] = s3; ridx[r] = cb + 3; }
        }
    }

    // ---- cross-thread argmin reduce (smaller index wins on tie) ----
#pragma unroll
    for (int r = 0; r < 4; r++) {
        sMin[ty * 4 + r][tx] = rmin[r];
        sIdx[ty * 4 + r][tx] = ridx[r];
    }
    __syncthreads();
    if (tid < TM) {
        float m = sMin[tid][0];
        int ix = sIdx[tid][0];
#pragma unroll
        for (int x = 1; x < 16; x++) {
            float v = sMin[tid][x];
            int i2 = sIdx[tid][x];
            if (v < m || (v == m && i2 < ix)) { m = v; ix = i2; }
        }
        sCode[tid] = ix;
        if (write_codes)
            out[(long)B * D_DIM + rowBase + tid] = (float)ix;
    }
    __syncthreads();

    // ---- epilogue: gather q, quantized = z + (q - z), commit partial ----
    float lsum = 0.f;
    const float4* z4 = (const float4*)z;
    const float4* e4 = (const float4*)embed;
    float4* o4 = (float4*)out;
#pragma unroll 4
    for (int i = tid; i < TM * (D_DIM / 4); i += NTHREADS) {
        int r = i >> 6;               // row in tile
        int c = i & 63;               // float4 within row
        int code = sCode[r];
        float4 qv = __ldg(&e4[(long)code * (D_DIM / 4) + c]);
        float4 zv = z4[(rowBase + r) * (D_DIM / 4) + c];
        float dx = __fsub_rn(qv.x, zv.x);
        float dy = __fsub_rn(qv.y, zv.y);
        float dz = __fsub_rn(qv.z, zv.z);
        float dw = __fsub_rn(qv.w, zv.w);
        float4 ov;
        ov.x = __fadd_rn(zv.x, dx);
        ov.y = __fadd_rn(zv.y, dy);
        ov.z = __fadd_rn(zv.z, dz);
        ov.w = __fadd_rn(zv.w, dw);
        o4[(rowBase + r) * (D_DIM / 4) + c] = ov;
        lsum += dx * dx + dy * dy + dz * dz + dw * dw;
    }
    sPart[tid] = lsum;
    __syncthreads();
#pragma unroll
    for (int s = NTHREADS / 2; s > 0; s >>= 1) {
        if (tid < s) sPart[tid] += sPart[tid + s];
        __syncthreads();
    }
    if (tid == 0) g_partials[blockIdx.x] = sPart[0];
}

__global__ void k_fin(float* __restrict__ out, int nblk, long BD, long B) {
    __shared__ double sp[256];
    int tid = threadIdx.x;
    double s = 0.0;
    for (int i = tid; i < nblk; i += 256) s += (double)g_partials[i];
    sp[tid] = s;
    __syncthreads();
    for (int st = 128; st > 0; st >>= 1) {
        if (tid < st) sp[tid] += sp[tid + st];
        __syncthreads();
    }
    if (tid == 0) {
        double commit = 0.25 * sp[0] / (double)BD;
        out[BD + B] = (float)commit;
    }
}

extern "C" void kernel_launch(void* const* d_in, const int* in_sizes, int n_in,
                              void* d_out, int out_size) {
    const float* z = (const float*)d_in[0];
    const float* embed = (const float*)d_in[1];
    float* out = (float*)d_out;

    int B = in_sizes[0] / D_DIM;
    long BD = (long)B * D_DIM;
    int nblk = B / TM;
    int write_codes = ((long)out_size >= BD + B) ? 1 : 0;
    int write_commit = ((long)out_size >= BD + B + 1) ? 1 : 0;

    k_rowsq_xla<<<(K_CODES + 1) / 2, 256>>>(embed, K_CODES, /*dest=*/0);
    k_rowsq_xla<<<(B + 1) / 2, 256>>>(z, B, /*dest=*/1);
    k_main<<<nblk, NTHREADS>>>(z, embed, out, B, write_codes);
    if (write_commit)
        k_fin<<<1, 256>>>(out, nblk, BD, (long)B);
}